// round 1
// baseline (speedup 1.0000x reference)
#include <cuda_runtime.h>
#include <math.h>

// Scratch: pooled features [B, 192]  (ligand -> [0,96), protein -> [96,192))
#define BATCH 4096
__device__ float g_feat[BATCH * 192];

// ---------------------------------------------------------------------------
// Fused conv1d(valid) + bias + ReLU + global max pool.
// One CTA per sample. Input row and transposed weights staged in dynamic smem.
// Each thread owns 8(channel) x 8(position) register tiles; x-window of 16
// floats is reused across the K kernel taps.
// ---------------------------------------------------------------------------
template <int VOCAB, int LEN, int K, int LENP, int FEAT_OFF>
__global__ __launch_bounds__(256, 1)
void conv_branch_kernel(const float* __restrict__ x,
                        const float* __restrict__ w,
                        const float* __restrict__ bias)
{
    constexpr int CH  = 96;
    constexpr int OUT = LEN - K + 1;
    constexpr int NT  = (OUT + 7) / 8;      // t-tiles
    constexpr int NC  = CH / 8;             // c-tiles = 12

    extern __shared__ float smem[];
    float* s_x = smem;                        // VOCAB * LENP
    float* s_w = s_x + VOCAB * LENP;          // (VOCAB*K) x CH  (transposed)
    float* s_b = s_w + VOCAB * K * CH;        // CH
    float* s_m = s_b + CH;                    // CH  (running max, >= 0)

    const int b   = blockIdx.x;
    const int tid = threadIdx.x;

    // ---- stage input (vectorized; LEN % 4 == 0 so float4s never cross rows)
    const float4* xg = reinterpret_cast<const float4*>(x + (size_t)b * VOCAB * LEN);
    for (int u = tid; u < VOCAB * LEN / 4; u += 256) {
        float4 v4 = xg[u];
        int flat = 4 * u;
        int v = flat / LEN;
        int t = flat - v * LEN;
        *reinterpret_cast<float4*>(&s_x[v * LENP + t]) = v4;
    }
    // zero the pad columns (read by the last tile's halo, masked in epilogue)
    for (int u = tid; u < VOCAB * (LENP - LEN); u += 256) {
        int v = u / (LENP - LEN);
        int t = LEN + (u - v * (LENP - LEN));
        s_x[v * LENP + t] = 0.f;
    }
    // ---- stage weights transposed: s_w[(v*K+k)*CH + c] = w[c, v, k]
    for (int f = tid; f < CH * VOCAB * K; f += 256) {
        int c  = f / (VOCAB * K);
        int vk = f - c * (VOCAB * K);
        s_w[vk * CH + c] = w[f];
    }
    if (tid < CH) { s_b[tid] = bias[tid]; s_m[tid] = 0.f; }
    __syncthreads();

    for (int tile = tid; tile < NC * NT; tile += 256) {
        int ct = tile / NT;
        int tt = tile - ct * NT;
        int c0 = ct * 8, t0 = tt * 8;

        float acc[8][8];
        #pragma unroll
        for (int i = 0; i < 8; i++)
            #pragma unroll
            for (int j = 0; j < 8; j++) acc[i][j] = 0.f;

        #pragma unroll 1
        for (int v = 0; v < VOCAB; v++) {
            float xr[16];
            const float4* xp = reinterpret_cast<const float4*>(&s_x[v * LENP + t0]);
            #pragma unroll
            for (int q = 0; q < 4; q++) {
                float4 t4 = xp[q];
                xr[4*q+0] = t4.x; xr[4*q+1] = t4.y;
                xr[4*q+2] = t4.z; xr[4*q+3] = t4.w;
            }
            #pragma unroll
            for (int k = 0; k < K; k++) {
                const float4* wp =
                    reinterpret_cast<const float4*>(&s_w[(v * K + k) * CH + c0]);
                float4 w0 = wp[0], w1 = wp[1];
                float wr[8] = {w0.x, w0.y, w0.z, w0.w, w1.x, w1.y, w1.z, w1.w};
                #pragma unroll
                for (int i = 0; i < 8; i++)
                    #pragma unroll
                    for (int j = 0; j < 8; j++)
                        acc[i][j] = fmaf(wr[i], xr[j + k], acc[i][j]);
            }
        }

        // bias + ReLU + local max (m starts at 0 == ReLU floor), masked tail
        #pragma unroll
        for (int i = 0; i < 8; i++) {
            float bb = s_b[c0 + i];
            float m = 0.f;
            #pragma unroll
            for (int j = 0; j < 8; j++)
                if (t0 + j < OUT) m = fmaxf(m, acc[i][j] + bb);
            // nonneg floats: int-bit compare is order-preserving
            atomicMax(reinterpret_cast<int*>(&s_m[c0 + i]), __float_as_int(m));
        }
    }
    __syncthreads();
    if (tid < CH) g_feat[(size_t)b * 192 + FEAT_OFF + tid] = s_m[tid];
}

// ---------------------------------------------------------------------------
// Per-sample: x = feat.reshape(6,32); gram = x^T x; L2-normalize; dot w_aff.
// One warp per sample; lane owns Gram column k=lane.
// ---------------------------------------------------------------------------
__global__ __launch_bounds__(256)
void gram_readout_kernel(const float* __restrict__ w_aff,
                         const float* __restrict__ b_aff,
                         float* __restrict__ out, int B)
{
    __shared__ float s_w[1024];
    __shared__ float s_f[8][192];
    const int tid  = threadIdx.x;
    const int warp = tid >> 5, lane = tid & 31;
    const int b = blockIdx.x * 8 + warp;

    for (int u = tid; u < 1024; u += 256) s_w[u] = w_aff[u];
    if (b < B)
        for (int u = lane; u < 192; u += 32) s_f[warp][u] = g_feat[(size_t)b * 192 + u];
    __syncthreads();
    if (b >= B) return;

    float xk[6];
    #pragma unroll
    for (int i = 0; i < 6; i++) xk[i] = s_f[warp][i * 32 + lane];

    float s1 = 0.f, s2 = 0.f;
    #pragma unroll 4
    for (int j = 0; j < 32; j++) {
        float g = 0.f;
        #pragma unroll
        for (int i = 0; i < 6; i++) g = fmaf(s_f[warp][i * 32 + j], xk[i], g);
        s2 = fmaf(g, g, s2);
        s1 = fmaf(g, s_w[j * 32 + lane], s1);
    }
    #pragma unroll
    for (int off = 16; off > 0; off >>= 1) {
        s1 += __shfl_xor_sync(0xffffffffu, s1, off);
        s2 += __shfl_xor_sync(0xffffffffu, s2, off);
    }
    if (lane == 0) out[b] = s1 / (sqrtf(s2) + 1e-12f) + b_aff[0];
}

// ---------------------------------------------------------------------------

extern "C" void kernel_launch(void* const* d_in, const int* in_sizes, int n_in,
                              void* d_out, int out_size)
{
    // positional defaults per metadata order
    const float* protein = (const float*)d_in[0];
    const float* ligand  = (const float*)d_in[1];
    const float* w_pro   = (const float*)d_in[2];
    const float* b_pro   = (const float*)d_in[3];
    const float* w_lig   = (const float*)d_in[4];
    const float* b_lig   = (const float*)d_in[5];
    const float* w_aff   = (const float*)d_in[6];
    const float* b_aff   = (const float*)d_in[7];

    // defensive: resolve by element count (all distinct except the two biases,
    // which keep their relative order)
    int seen96 = 0;
    for (int i = 0; i < n_in; i++) {
        long long s = in_sizes[i];
        const float* p = (const float*)d_in[i];
        if      (s == (long long)BATCH * 25 * 1000) protein = p;
        else if (s == (long long)BATCH * 64 * 100)  ligand  = p;
        else if (s == 96LL * 25 * 8)                w_pro   = p;
        else if (s == 96LL * 64 * 4)                w_lig   = p;
        else if (s == 1024LL)                       w_aff   = p;
        else if (s == 96LL) { if (seen96++ == 0) b_pro = p; else b_lig = p; }
        else if (s == 1LL)                          b_aff   = p;
    }

    float* out = (float*)d_out;

    constexpr int PRO_SMEM = (25 * 1008 + 25 * 8 * 96 + 96 + 96) * 4;  // 178368
    constexpr int LIG_SMEM = (64 * 112  + 64 * 4 * 96 + 96 + 96) * 4;  // 127744

    cudaFuncSetAttribute(conv_branch_kernel<25, 1000, 8, 1008, 96>,
                         cudaFuncAttributeMaxDynamicSharedMemorySize, PRO_SMEM);
    cudaFuncSetAttribute(conv_branch_kernel<64, 100, 4, 112, 0>,
                         cudaFuncAttributeMaxDynamicSharedMemorySize, LIG_SMEM);

    conv_branch_kernel<64, 100, 4, 112, 0><<<BATCH, 256, LIG_SMEM>>>(ligand, w_lig, b_lig);
    conv_branch_kernel<25, 1000, 8, 1008, 96><<<BATCH, 256, PRO_SMEM>>>(protein, w_pro, b_pro);
    gram_readout_kernel<<<BATCH / 8, 256>>>(w_aff, b_aff, out, BATCH);
}

// round 2
// speedup vs baseline: 1.0943x; 1.0943x over previous
#include <cuda_runtime.h>
#include <math.h>

// Scratch: pooled features [B, 192]  (ligand -> [0,96), protein -> [96,192))
#define BATCH 4096
__device__ float g_feat[BATCH * 192];

typedef unsigned long long u64;

// packed fp32x2 FMA: d = a*b + d  (Blackwell full-width FP32 path)
__device__ __forceinline__ void ffma2(u64& d, u64 a, u64 b)
{
    asm("fma.rn.f32x2 %0, %1, %2, %0;" : "+l"(d) : "l"(a), "l"(b));
}
// pack {x, x} into a 64-bit lane pair
__device__ __forceinline__ u64 dup2(float x)
{
    u64 r;
    asm("mov.b64 %0, {%1, %1};" : "=l"(r) : "f"(x));
    return r;
}

// ---------------------------------------------------------------------------
// Fused conv1d(valid) + bias + ReLU + global max pool.
// One CTA per sample. Input row and transposed weights staged in dynamic smem.
// Each thread owns an 8(channel) x 8(position) accumulator tile kept as
// 4x8 packed f32x2 pairs (pairs along the channel dim, so float4 weight loads
// provide packed operands for free; x is broadcast-duplicated once per row).
// ---------------------------------------------------------------------------
template <int VOCAB, int LEN, int K, int LENP, int FEAT_OFF>
__global__ __launch_bounds__(256, 1)
void conv_branch_kernel(const float* __restrict__ x,
                        const float* __restrict__ w,
                        const float* __restrict__ bias)
{
    constexpr int CH  = 96;
    constexpr int OUT = LEN - K + 1;
    constexpr int NT  = (OUT + 7) / 8;      // t-tiles
    constexpr int NC  = CH / 8;             // c-tiles = 12
    constexpr int XW  = 8 + K - 1;          // x-window width actually used

    extern __shared__ float smem[];
    float* s_x = smem;                        // VOCAB * LENP
    float* s_w = s_x + VOCAB * LENP;          // (VOCAB*K) x CH  (transposed)
    float* s_b = s_w + VOCAB * K * CH;        // CH
    float* s_m = s_b + CH;                    // CH  (running max, >= 0)

    const int b   = blockIdx.x;
    const int tid = threadIdx.x;

    // ---- stage input (vectorized; LEN % 4 == 0 so float4s never cross rows)
    const float4* xg = reinterpret_cast<const float4*>(x + (size_t)b * VOCAB * LEN);
    for (int u = tid; u < VOCAB * LEN / 4; u += 256) {
        float4 v4 = xg[u];
        int flat = 4 * u;
        int v = flat / LEN;
        int t = flat - v * LEN;
        *reinterpret_cast<float4*>(&s_x[v * LENP + t]) = v4;
    }
    // zero the pad columns (read by the last tile's halo, masked in epilogue)
    for (int u = tid; u < VOCAB * (LENP - LEN); u += 256) {
        int v = u / (LENP - LEN);
        int t = LEN + (u - v * (LENP - LEN));
        s_x[v * LENP + t] = 0.f;
    }
    // ---- stage weights transposed: s_w[(v*K+k)*CH + c] = w[c, v, k]
    for (int f = tid; f < CH * VOCAB * K; f += 256) {
        int c  = f / (VOCAB * K);
        int vk = f - c * (VOCAB * K);
        s_w[vk * CH + c] = w[f];
    }
    if (tid < CH) { s_b[tid] = bias[tid]; s_m[tid] = 0.f; }
    __syncthreads();

    for (int tile = tid; tile < NC * NT; tile += 256) {
        int ct = tile / NT;
        int tt = tile - ct * NT;
        int c0 = ct * 8, t0 = tt * 8;

        // acc2[p][j]: channel pair (c0+2p, c0+2p+1) at position t0+j
        u64 acc2[4][8];
        #pragma unroll
        for (int p = 0; p < 4; p++)
            #pragma unroll
            for (int j = 0; j < 8; j++) acc2[p][j] = 0ull;

        #pragma unroll 1
        for (int v = 0; v < VOCAB; v++) {
            // x window as packed duplicates {x,x}
            float xr[16];
            const float4* xp = reinterpret_cast<const float4*>(&s_x[v * LENP + t0]);
            #pragma unroll
            for (int q = 0; q < 4; q++) {
                float4 t4 = xp[q];
                xr[4*q+0] = t4.x; xr[4*q+1] = t4.y;
                xr[4*q+2] = t4.z; xr[4*q+3] = t4.w;
            }
            u64 xx[XW];
            #pragma unroll
            for (int m = 0; m < XW; m++) xx[m] = dup2(xr[m]);

            #pragma unroll
            for (int k = 0; k < K; k++) {
                const u64* wp =
                    reinterpret_cast<const u64*>(&s_w[(v * K + k) * CH + c0]);
                u64 w2[4];
                #pragma unroll
                for (int p = 0; p < 4; p++) w2[p] = wp[p];
                #pragma unroll
                for (int p = 0; p < 4; p++)
                    #pragma unroll
                    for (int j = 0; j < 8; j++)
                        ffma2(acc2[p][j], w2[p], xx[j + k]);
            }
        }

        // bias + ReLU + local max (m starts at 0 == ReLU floor), masked tail
        #pragma unroll
        for (int p = 0; p < 4; p++) {
            float2 bb = *reinterpret_cast<const float2*>(&s_b[c0 + 2 * p]);
            float mlo = 0.f, mhi = 0.f;
            #pragma unroll
            for (int j = 0; j < 8; j++) {
                if (t0 + j < OUT) {
                    float2 a = *reinterpret_cast<const float2*>(&acc2[p][j]);
                    mlo = fmaxf(mlo, a.x + bb.x);
                    mhi = fmaxf(mhi, a.y + bb.y);
                }
            }
            // nonneg floats: int-bit compare is order-preserving
            atomicMax(reinterpret_cast<int*>(&s_m[c0 + 2 * p]),     __float_as_int(mlo));
            atomicMax(reinterpret_cast<int*>(&s_m[c0 + 2 * p + 1]), __float_as_int(mhi));
        }
    }
    __syncthreads();
    if (tid < CH) g_feat[(size_t)b * 192 + FEAT_OFF + tid] = s_m[tid];
}

// ---------------------------------------------------------------------------
// Per-sample: x = feat.reshape(6,32); gram = x^T x; L2-normalize; dot w_aff.
// One warp per sample; lane owns Gram column k=lane.
// ---------------------------------------------------------------------------
__global__ __launch_bounds__(256)
void gram_readout_kernel(const float* __restrict__ w_aff,
                         const float* __restrict__ b_aff,
                         float* __restrict__ out, int B)
{
    __shared__ float s_w[1024];
    __shared__ float s_f[8][192];
    const int tid  = threadIdx.x;
    const int warp = tid >> 5, lane = tid & 31;
    const int b = blockIdx.x * 8 + warp;

    for (int u = tid; u < 1024; u += 256) s_w[u] = w_aff[u];
    if (b < B)
        for (int u = lane; u < 192; u += 32) s_f[warp][u] = g_feat[(size_t)b * 192 + u];
    __syncthreads();
    if (b >= B) return;

    float xk[6];
    #pragma unroll
    for (int i = 0; i < 6; i++) xk[i] = s_f[warp][i * 32 + lane];

    float s1 = 0.f, s2 = 0.f;
    #pragma unroll 4
    for (int j = 0; j < 32; j++) {
        float g = 0.f;
        #pragma unroll
        for (int i = 0; i < 6; i++) g = fmaf(s_f[warp][i * 32 + j], xk[i], g);
        s2 = fmaf(g, g, s2);
        s1 = fmaf(g, s_w[j * 32 + lane], s1);
    }
    #pragma unroll
    for (int off = 16; off > 0; off >>= 1) {
        s1 += __shfl_xor_sync(0xffffffffu, s1, off);
        s2 += __shfl_xor_sync(0xffffffffu, s2, off);
    }
    if (lane == 0) out[b] = s1 / (sqrtf(s2) + 1e-12f) + b_aff[0];
}

// ---------------------------------------------------------------------------

extern "C" void kernel_launch(void* const* d_in, const int* in_sizes, int n_in,
                              void* d_out, int out_size)
{
    // positional defaults per metadata order
    const float* protein = (const float*)d_in[0];
    const float* ligand  = (const float*)d_in[1];
    const float* w_pro   = (const float*)d_in[2];
    const float* b_pro   = (const float*)d_in[3];
    const float* w_lig   = (const float*)d_in[4];
    const float* b_lig   = (const float*)d_in[5];
    const float* w_aff   = (const float*)d_in[6];
    const float* b_aff   = (const float*)d_in[7];

    // defensive: resolve by element count (all distinct except the two biases,
    // which keep their relative order)
    int seen96 = 0;
    for (int i = 0; i < n_in; i++) {
        long long s = in_sizes[i];
        const float* p = (const float*)d_in[i];
        if      (s == (long long)BATCH * 25 * 1000) protein = p;
        else if (s == (long long)BATCH * 64 * 100)  ligand  = p;
        else if (s == 96LL * 25 * 8)                w_pro   = p;
        else if (s == 96LL * 64 * 4)                w_lig   = p;
        else if (s == 1024LL)                       w_aff   = p;
        else if (s == 96LL) { if (seen96++ == 0) b_pro = p; else b_lig = p; }
        else if (s == 1LL)                          b_aff   = p;
    }

    float* out = (float*)d_out;

    constexpr int PRO_SMEM = (25 * 1008 + 25 * 8 * 96 + 96 + 96) * 4;  // 178368
    constexpr int LIG_SMEM = (64 * 112  + 64 * 4 * 96 + 96 + 96) * 4;  // 127744

    cudaFuncSetAttribute(conv_branch_kernel<25, 1000, 8, 1008, 96>,
                         cudaFuncAttributeMaxDynamicSharedMemorySize, PRO_SMEM);
    cudaFuncSetAttribute(conv_branch_kernel<64, 100, 4, 112, 0>,
                         cudaFuncAttributeMaxDynamicSharedMemorySize, LIG_SMEM);

    conv_branch_kernel<64, 100, 4, 112, 0><<<BATCH, 256, LIG_SMEM>>>(ligand, w_lig, b_lig);
    conv_branch_kernel<25, 1000, 8, 1008, 96><<<BATCH, 256, PRO_SMEM>>>(protein, w_pro, b_pro);
    gram_readout_kernel<<<BATCH / 8, 256>>>(w_aff, b_aff, out, BATCH);
}